// round 3
// baseline (speedup 1.0000x reference)
#include <cuda_runtime.h>
#include <cstdint>

/*
 Theory: mask of top-262144 entries of zero-diagonal outer(p,p), N=8192.
 1) counting-sort p by hi-16 sortable key + per-bin insertion fix
 2) one-block binary search for conservative lower bound Tlo <= T*
    using count(prod>T) = sum_i cdf(T/p_i) with directed rounding + 2-bin margin
 3) enumerate all pairs with product > Tlo (prefix/suffix per sorted row)
 4) exact K-th key via hi16 then lo16 histograms; ties by smallest flat index
 5) output: float4 zero-fill (store-bound ~30us) + scattered 1.0 writes
*/

#define N      8192
#define LOGN   13
#define KTOP   262144u
#define NBIN   65536
#define CAP    (4u<<20)
#define TIECAP 4096

__device__ unsigned g_h16[NBIN];
__device__ unsigned g_S[NBIN + 1];
__device__ unsigned g_off[NBIN];
__device__ float    g_sval[N];
__device__ int      g_sidx[N];
__device__ float    g_Tlo;
__device__ unsigned g_keys[CAP];
__device__ unsigned g_flats[CAP];
__device__ unsigned g_cnt;
__device__ unsigned g_h1[NBIN];
__device__ unsigned g_h2[NBIN];
__device__ unsigned g_B, g_Ghi;
__device__ unsigned g_TkKey, g_r;
__device__ unsigned g_tie[TIECAP];
__device__ unsigned g_ntie;
__device__ unsigned g_cut;

__device__ __forceinline__ unsigned fkey(float f) {
    unsigned u = __float_as_uint(f);
    return u ^ (((unsigned)((int)u >> 31)) | 0x80000000u);
}
__device__ __forceinline__ float unflip(unsigned k) {
    unsigned u = (k & 0x80000000u) ? (k ^ 0x80000000u) : ~k;
    return __uint_as_float(u);
}

__global__ void k_init() {
    unsigned t = blockIdx.x * blockDim.x + threadIdx.x;
    unsigned st = gridDim.x * blockDim.x;
    for (unsigned i = t; i < NBIN; i += st) { g_h16[i] = 0; g_h1[i] = 0; g_h2[i] = 0; }
    if (t == 0) { g_cnt = 0; g_ntie = 0; g_B = 0; g_Ghi = 0; g_TkKey = 0; g_r = 0; g_cut = 0; }
}

__global__ void k_hist(const float* __restrict__ p) {
    int i = blockIdx.x * blockDim.x + threadIdx.x;
    if (i < N) atomicAdd(&g_h16[fkey(p[i]) >> 16], 1u);
}

/* suffix (descending) scan: S[b] = count of keys in bins >= b */
__global__ void k_scan() {
    __shared__ unsigned cur[1024];
    int t = threadIdx.x;
    int base = t * 64;
    unsigned ct = 0;
    for (int j = 0; j < 64; j++) ct += g_h16[base + j];
    cur[t] = ct; __syncthreads();
    for (int d = 1; d < 1024; d <<= 1) {
        unsigned v2 = cur[t] + ((t + d < 1024) ? cur[t + d] : 0u);
        __syncthreads(); cur[t] = v2; __syncthreads();
    }
    unsigned run = cur[t] - ct;
    for (int j = 63; j >= 0; j--) {
        unsigned h = g_h16[base + j];
        run += h;
        g_S[base + j] = run;
        g_off[base + j] = run - h;
    }
    if (t == 0) g_S[NBIN] = 0;
}

__global__ void k_scatter(const float* __restrict__ p) {
    int i = blockIdx.x * blockDim.x + threadIdx.x;
    if (i < N) {
        float v = p[i];
        unsigned b = fkey(v) >> 16;
        unsigned pos = atomicAdd(&g_off[b], 1u);
        g_sval[pos] = v;
        g_sidx[pos] = i;
    }
}

__global__ void k_fix() {
    int b = blockIdx.x * blockDim.x + threadIdx.x;
    if (b >= NBIN) return;
    int n = (int)g_h16[b];
    if (n < 2) return;
    int start = (int)g_S[b] - n;
    for (int i = start + 1; i < start + n; i++) {
        float kv = g_sval[i]; int ki = g_sidx[i];
        int j = i - 1;
        while (j >= start && g_sval[j] < kv) {
            g_sval[j + 1] = g_sval[j]; g_sidx[j + 1] = g_sidx[j]; j--;
        }
        g_sval[j + 1] = kv; g_sidx[j + 1] = ki;
    }
}

/* one block: binary search over fine bin edges for conservative Tlo <= T* */
__global__ void k_bracket(const float* __restrict__ p) {
    __shared__ unsigned red[1024];
    __shared__ unsigned s_lo, s_hi;
    int t = threadIdx.x;
    float pv[8];
    #pragma unroll
    for (int j = 0; j < 8; j++) pv[j] = p[t + j * 1024];
    if (t == 0) { s_lo = 32768u; s_hi = 65535u; }
    __syncthreads();
    for (int iter = 0; iter < 15; iter++) {
        unsigned mid = (s_lo + s_hi) >> 1;
        float T = unflip(mid << 16);
        unsigned cnt = 0;
        #pragma unroll
        for (int j = 0; j < 8; j++) {
            float v = pv[j];
            if (v > 0.0f) {
                float c = __fdiv_ru(T, v);
                unsigned b = fkey(c) >> 16;
                cnt += (b <= 65533u) ? g_S[b + 2] : 0u;
            } else if (v < 0.0f) {
                float c = __fdiv_rd(T, v);
                unsigned b = fkey(c) >> 16;
                cnt += (b >= 1u) ? ((unsigned)N - g_S[b - 1]) : 0u;
            }
        }
        red[t] = cnt; __syncthreads();
        for (int s = 512; s > 0; s >>= 1) {
            if (t < s) red[t] += red[t + s];
            __syncthreads();
        }
        if (t == 0) {
            if (red[0] >= KTOP + (unsigned)N) s_lo = mid; else s_hi = mid;
        }
        __syncthreads();
    }
    if (t == 0) g_Tlo = unflip(((unsigned)s_lo) << 16);
}

/* one warp per sorted row: binary-search boundary, emit qualifying pairs */
__global__ void k_enum() {
    int gtid = blockIdx.x * blockDim.x + threadIdx.x;
    int t = gtid >> 5;
    int lane = gtid & 31;
    if (t >= N) return;
    float v = g_sval[t];
    float Tlo = g_Tlo;
    if (v == 0.0f) return;
    int sbase, cnt;
    if (v > 0.0f) {
        int lo = 0, hi = N;
        while (lo < hi) { int m = (lo + hi) >> 1; if (v * __ldg(&g_sval[m]) > Tlo) lo = m + 1; else hi = m; }
        sbase = 0; cnt = lo;
    } else {
        int lo = 0, hi = N;
        while (lo < hi) { int m = (lo + hi) >> 1; if (!(v * __ldg(&g_sval[m]) > Tlo)) lo = m + 1; else hi = m; }
        sbase = lo; cnt = N - lo;
    }
    if (cnt <= 0) return;
    unsigned base = 0;
    if (lane == 0) base = atomicAdd(&g_cnt, (unsigned)cnt);
    base = __shfl_sync(0xffffffffu, base, 0);
    if (base + (unsigned)cnt > CAP) return;
    unsigned fbase = ((unsigned)g_sidx[t]) << LOGN;
    for (int k = lane; k < cnt; k += 32) {
        int s = sbase + k;
        unsigned key = (s == t) ? 0u : fkey(v * __ldg(&g_sval[s]));
        g_keys[base + k]  = key;
        g_flats[base + k] = fbase + (unsigned)__ldg(&g_sidx[s]);
    }
}

__global__ void k_hsel1() {
    unsigned M = min(g_cnt, CAP);
    unsigned t = blockIdx.x * blockDim.x + threadIdx.x;
    unsigned st = gridDim.x * blockDim.x;
    for (unsigned i = t; i < M; i += st) atomicAdd(&g_h1[g_keys[i] >> 16], 1u);
}

__global__ void k_sel1() {
    __shared__ unsigned cur[1024];
    int t = threadIdx.x;
    int base = t * 64;
    unsigned ct = 0;
    for (int j = 0; j < 64; j++) ct += g_h1[base + j];
    cur[t] = ct; __syncthreads();
    for (int d = 1; d < 1024; d <<= 1) {
        unsigned v2 = cur[t] + ((t + d < 1024) ? cur[t + d] : 0u);
        __syncthreads(); cur[t] = v2; __syncthreads();
    }
    unsigned g = cur[t] - ct;
    for (int j = 63; j >= 0; j--) {
        unsigned h = g_h1[base + j];
        if (h && g < KTOP && KTOP <= g + h) { g_B = (unsigned)(base + j); g_Ghi = g; }
        g += h;
    }
}

__global__ void k_hsel2() {
    unsigned M = min(g_cnt, CAP);
    unsigned B = g_B;
    unsigned t = blockIdx.x * blockDim.x + threadIdx.x;
    unsigned st = gridDim.x * blockDim.x;
    for (unsigned i = t; i < M; i += st) {
        unsigned k = g_keys[i];
        if ((k >> 16) == B) atomicAdd(&g_h2[k & 65535u], 1u);
    }
}

__global__ void k_sel2() {
    __shared__ unsigned cur[1024];
    int t = threadIdx.x;
    int base = t * 64;
    unsigned K2 = KTOP - g_Ghi;
    unsigned ct = 0;
    for (int j = 0; j < 64; j++) ct += g_h2[base + j];
    cur[t] = ct; __syncthreads();
    for (int d = 1; d < 1024; d <<= 1) {
        unsigned v2 = cur[t] + ((t + d < 1024) ? cur[t + d] : 0u);
        __syncthreads(); cur[t] = v2; __syncthreads();
    }
    unsigned g = cur[t] - ct;
    for (int j = 63; j >= 0; j--) {
        unsigned h = g_h2[base + j];
        if (h && g < K2 && K2 <= g + h) {
            g_TkKey = (g_B << 16) | (unsigned)(base + j);
            g_r = K2 - g;
        }
        g += h;
    }
}

__global__ void k_ties() {
    unsigned M = min(g_cnt, CAP);
    unsigned Tk = g_TkKey;
    unsigned t = blockIdx.x * blockDim.x + threadIdx.x;
    unsigned st = gridDim.x * blockDim.x;
    for (unsigned i = t; i < M; i += st) {
        if (g_keys[i] == Tk) {
            unsigned pp = atomicAdd(&g_ntie, 1u);
            if (pp < TIECAP) g_tie[pp] = g_flats[i];
        }
    }
}

__global__ void k_tiecut() {
    int t = threadIdx.x;
    unsigned nt = g_ntie;
    if (nt > TIECAP) nt = TIECAP;
    unsigned r = g_r;
    if (r >= nt) { if (t == 0) g_cut = 0xFFFFFFFFu; return; }
    for (unsigned i = t; i < nt; i += 1024) {
        unsigned x = g_tie[i];
        unsigned rk = 0;
        for (unsigned j = 0; j < nt; j++) rk += (g_tie[j] < x) ? 1u : 0u;
        if (rk == r) g_cut = x;
    }
}

__global__ void k_zero(float4* __restrict__ out4) {
    unsigned t = blockIdx.x * blockDim.x + threadIdx.x;
    unsigned st = gridDim.x * blockDim.x;
    float4 z = make_float4(0.f, 0.f, 0.f, 0.f);
    unsigned total = ((unsigned)N * (unsigned)N) / 4u;
    for (unsigned i = t; i < total; i += st) out4[i] = z;
}

__global__ void k_scatout(float* __restrict__ out) {
    unsigned M = min(g_cnt, CAP);
    unsigned Tk = g_TkKey, cut = g_cut;
    unsigned t = blockIdx.x * blockDim.x + threadIdx.x;
    unsigned st = gridDim.x * blockDim.x;
    for (unsigned i = t; i < M; i += st) {
        unsigned k = g_keys[i];
        if (k > Tk || (k == Tk && g_flats[i] < cut)) out[g_flats[i]] = 1.0f;
    }
}

extern "C" void kernel_launch(void* const* d_in, const int* in_sizes, int n_in,
                              void* d_out, int out_size) {
    const float* p = (const float*)d_in[0];
    float* out = (float*)d_out;
    (void)in_sizes; (void)n_in; (void)out_size;

    k_init<<<256, 256>>>();
    k_hist<<<(N + 255) / 256, 256>>>(p);
    k_scan<<<1, 1024>>>();
    k_scatter<<<(N + 255) / 256, 256>>>(p);
    k_fix<<<NBIN / 256, 256>>>();
    k_bracket<<<1, 1024>>>(p);
    k_enum<<<(N * 32) / 256, 256>>>();
    k_hsel1<<<512, 256>>>();
    k_sel1<<<1, 1024>>>();
    k_hsel2<<<512, 256>>>();
    k_sel2<<<1, 1024>>>();
    k_ties<<<512, 256>>>();
    k_tiecut<<<1, 1024>>>();
    k_zero<<<2048, 256>>>((float4*)out);
    k_scatout<<<512, 256>>>(out);
}

// round 4
// speedup vs baseline: 1.0732x; 1.0732x over previous
#include <cuda_runtime.h>
#include <cstdint>

/*
 Top-K mask of zero-diagonal outer(p,p), N=8192, K=262144.
 Kernel 1 (single block): on-chip counting sort of p, then exact bisection
 over the uint32 sortable-key space using per-row binary searches with the
 raw multiply predicate (exact, monotone). Produces exact threshold float,
 and the tie cut (smallest-flat-index-first, matching jax.lax.top_k).
 Kernel 2 (wide): fused output pass, one float4 store stream over 268MB.
*/

#define N      8192
#define KTOP   262144u
#define NBIN   65536
#define TIECAP 4096

__device__ unsigned g_h16[NBIN];
__device__ unsigned g_S[NBIN];
__device__ unsigned g_off[NBIN];
__device__ float    g_thr;
__device__ unsigned g_cut;

__device__ __forceinline__ unsigned fkey(float f) {
    unsigned u = __float_as_uint(f);
    return u ^ (((unsigned)((int)u >> 31)) | 0x80000000u);
}
__device__ __forceinline__ float unflip(unsigned k) {
    unsigned u = (k & 0x80000000u) ? (k ^ 0x80000000u) : ~k;
    return __uint_as_float(u);
}

/* #{m in [0,N): fl(v*s[m]) >= T}, s sorted descending */
__device__ __forceinline__ unsigned bs_count(float v, float T, const float* s) {
    if (v > 0.0f) {
        int lo = 0, hi = N;
        while (lo < hi) { int m = (lo + hi) >> 1; if (v * s[m] >= T) lo = m + 1; else hi = m; }
        return (unsigned)lo;
    }
    if (v < 0.0f) {
        int lo = 0, hi = N;
        while (lo < hi) { int m = (lo + hi) >> 1; if (v * s[m] >= T) hi = m; else lo = m + 1; }
        return (unsigned)(N - lo);
    }
    return 0u;
}

__global__ void k_select(const float* __restrict__ p) {
    extern __shared__ unsigned char sm[];
    float*    s_val = (float*)sm;                       /* 32KB */
    int*      s_idx = (int*)(sm + 32768);               /* 32KB */
    unsigned* s_tie = (unsigned*)(sm + 65536);          /* 16KB */
    __shared__ unsigned cur[1024];
    __shared__ unsigned s_red[32];
    __shared__ unsigned s_total, s_lo, s_hi, s_ntie, s_cut;

    int t = threadIdx.x;  /* 1024 threads */

    /* ---- zero hist ---- */
    for (int i = t; i < NBIN; i += 1024) g_h16[i] = 0;
    __syncthreads();

    /* ---- hist of p (hi-16 sortable key) ---- */
    float pv[8];
    #pragma unroll
    for (int j = 0; j < 8; j++) {
        pv[j] = p[t + j * 1024];
        atomicAdd(&g_h16[fkey(pv[j]) >> 16], 1u);
    }
    __syncthreads();

    /* ---- suffix scan: g_S[b] = #keys in bins >= b ---- */
    {
        int base = t * 64;
        unsigned ct = 0;
        for (int j = 0; j < 64; j++) ct += g_h16[base + j];
        cur[t] = ct; __syncthreads();
        for (int d = 1; d < 1024; d <<= 1) {
            unsigned v2 = cur[t] + ((t + d < 1024) ? cur[t + d] : 0u);
            __syncthreads(); cur[t] = v2; __syncthreads();
        }
        unsigned run = cur[t] - ct;
        for (int j = 63; j >= 0; j--) {
            unsigned h = g_h16[base + j];
            run += h;
            g_S[base + j] = run;
            g_off[base + j] = run - h;
        }
    }
    __syncthreads();

    /* ---- scatter into shared (descending by bin) ---- */
    #pragma unroll
    for (int j = 0; j < 8; j++) {
        unsigned b = fkey(pv[j]) >> 16;
        unsigned pos = atomicAdd(&g_off[b], 1u);
        s_val[pos] = pv[j];
        s_idx[pos] = t + j * 1024;
    }
    __syncthreads();

    /* ---- per-bin insertion fix (exact descending order) ---- */
    for (int b = t; b < NBIN; b += 1024) {
        int n = (int)g_h16[b];
        if (n < 2) continue;
        int start = (int)g_S[b] - n;
        for (int i = start + 1; i < start + n; i++) {
            float kv = s_val[i]; int ki = s_idx[i];
            int j = i - 1;
            while (j >= start && s_val[j] < kv) {
                s_val[j + 1] = s_val[j]; s_idx[j + 1] = s_idx[j]; j--;
            }
            s_val[j + 1] = kv; s_idx[j + 1] = ki;
        }
    }
    __syncthreads();

    /* row values for this thread (8 rows, sorted positions t + j*1024) */
    float rv[8];
    #pragma unroll
    for (int j = 0; j < 8; j++) rv[j] = s_val[t + j * 1024];

    /* ---- exact bisection over key space ---- */
    if (t == 0) { s_lo = 0x80000000u; s_hi = 0xFFFFFFFFu; }
    __syncthreads();
    for (;;) {
        unsigned lo = s_lo, hi = s_hi;
        if (hi - lo <= 1u) break;
        unsigned mid = lo + ((hi - lo) >> 1);
        float T = unflip(mid);
        unsigned c = 0;
        #pragma unroll
        for (int j = 0; j < 8; j++) {
            c += bs_count(rv[j], T, s_val);
            if (rv[j] * rv[j] >= T) c -= 1u;   /* remove diagonal pair */
        }
        #pragma unroll
        for (int d = 16; d > 0; d >>= 1) c += __shfl_down_sync(0xffffffffu, c, d);
        if ((t & 31) == 0) s_red[t >> 5] = c;
        __syncthreads();
        if (t == 0) {
            unsigned s = 0;
            for (int i = 0; i < 32; i++) s += s_red[i];
            if (s >= KTOP) s_lo = mid; else s_hi = mid;
        }
        __syncthreads();
    }
    unsigned Tk = s_lo;
    float thr  = unflip(Tk);
    float thr1 = unflip(Tk + 1u);

    /* ---- strict-above count G at Tk+1 -> tie budget r ---- */
    {
        unsigned c = 0;
        #pragma unroll
        for (int j = 0; j < 8; j++) {
            c += bs_count(rv[j], thr1, s_val);
            if (rv[j] * rv[j] >= thr1) c -= 1u;
        }
        #pragma unroll
        for (int d = 16; d > 0; d >>= 1) c += __shfl_down_sync(0xffffffffu, c, d);
        if ((t & 31) == 0) s_red[t >> 5] = c;
        __syncthreads();
        if (t == 0) {
            unsigned s = 0;
            for (int i = 0; i < 32; i++) s += s_red[i];
            s_total = s;
        }
        __syncthreads();
    }
    unsigned r = KTOP - s_total;

    /* ---- collect tie pairs (value exactly == thr), skip diagonal ---- */
    if (t == 0) s_ntie = 0;
    __syncthreads();
    #pragma unroll
    for (int j = 0; j < 8; j++) {
        int row = t + j * 1024;
        float v = rv[j];
        if (v == 0.0f) continue;
        unsigned cA = bs_count(v, thr,  s_val);
        unsigned cB = bs_count(v, thr1, s_val);
        if (cA == cB) continue;
        unsigned fb = ((unsigned)s_idx[row]) << 13;
        if (v > 0.0f) {
            for (unsigned m = cB; m < cA; m++) {
                if ((int)m == row) continue;
                unsigned pos = atomicAdd(&s_ntie, 1u);
                if (pos < TIECAP) s_tie[pos] = fb + (unsigned)s_idx[m];
            }
        } else {
            for (unsigned m = (unsigned)N - cA; m < (unsigned)N - cB; m++) {
                if ((int)m == row) continue;
                unsigned pos = atomicAdd(&s_ntie, 1u);
                if (pos < TIECAP) s_tie[pos] = fb + (unsigned)s_idx[m];
            }
        }
    }
    __syncthreads();

    /* ---- cut = flat with rank r among ties (include flats < cut) ---- */
    unsigned nt = min(s_ntie, (unsigned)TIECAP);
    if (t == 0) s_cut = (r >= nt) ? 0xFFFFFFFFu : 0u;
    __syncthreads();
    if (r < nt) {
        for (unsigned i = t; i < nt; i += 1024) {
            unsigned x = s_tie[i];
            unsigned rk = 0;
            for (unsigned j = 0; j < nt; j++) rk += (s_tie[j] < x) ? 1u : 0u;
            if (rk == r) s_cut = x;
        }
    }
    __syncthreads();
    if (t == 0) { g_thr = thr; g_cut = s_cut; }
}

/* ---- fused output: 1.0 iff in top-K, else 0.0 ---- */
__device__ __forceinline__ float edgev(float v, float thr, unsigned flat, unsigned cut, bool diag) {
    bool ok = ((v > thr) | ((v == thr) & (flat < cut))) & (!diag);
    return ok ? 1.0f : 0.0f;
}

__global__ void k_out(const float* __restrict__ p, float4* __restrict__ out) {
    int row = blockIdx.y;
    float pi = __ldg(p + row);
    float thr = g_thr;
    unsigned cut = g_cut;
    const float4* __restrict__ q4 = (const float4*)p;
    int f0 = blockIdx.x * 1024 + threadIdx.x;
    unsigned fbase = ((unsigned)row) << 13;
    unsigned outrow = ((unsigned)row) << 11;     /* row * 2048 float4 */
    #pragma unroll
    for (int k = 0; k < 4; k++) {
        int f = f0 + k * 256;
        float4 q = __ldg(q4 + f);
        unsigned j0 = ((unsigned)f) << 2;
        float4 o;
        o.x = edgev(pi * q.x, thr, fbase + j0 + 0u, cut, (j0 + 0u) == (unsigned)row);
        o.y = edgev(pi * q.y, thr, fbase + j0 + 1u, cut, (j0 + 1u) == (unsigned)row);
        o.z = edgev(pi * q.z, thr, fbase + j0 + 2u, cut, (j0 + 2u) == (unsigned)row);
        o.w = edgev(pi * q.w, thr, fbase + j0 + 3u, cut, (j0 + 3u) == (unsigned)row);
        out[outrow + (unsigned)f] = o;
    }
}

extern "C" void kernel_launch(void* const* d_in, const int* in_sizes, int n_in,
                              void* d_out, int out_size) {
    const float* p = (const float*)d_in[0];
    float* out = (float*)d_out;
    (void)in_sizes; (void)n_in; (void)out_size;

    static int smem_set = 0;
    const int SMEM = 32768 + 32768 + TIECAP * 4;   /* 81920 B dynamic */
    if (!smem_set) {
        cudaFuncSetAttribute(k_select, cudaFuncAttributeMaxDynamicSharedMemorySize, SMEM);
        smem_set = 1;
    }

    k_select<<<1, 1024, SMEM>>>(p);

    dim3 grid(2, N);
    k_out<<<grid, 256>>>(p, (float4*)out);
}

// round 6
// speedup vs baseline: 1.4205x; 1.3237x over previous
#include <cuda_runtime.h>
#include <cstdint>

/*
 Top-K mask of zero-diagonal outer(p,p), N=8192, K=262144.
 k_select (1 block, 1024 thr, 128KB smem):
   - counting sort of p fully in shared (16384-bin hi-14-key hist + per-run fix)
   - exact 31-step bisection over uint32 sortable-key space; contiguous-row
     assignment; per-row sign-aware warm-start boundary intervals
   - exact tie budget + smallest-flat-index cut (jax top_k stability)
 k_out: fused 268MB float4 store pass (store-roofline bound).
*/

#define N      8192
#define KTOP   262144u
#define NBINS  16384      /* hi-14 sortable-key bins */
#define KSHIFT 18
#define TIECAP 4096

__device__ float    g_thr;
__device__ unsigned g_cut;

__device__ __forceinline__ unsigned fkey(float f) {
    unsigned u = __float_as_uint(f);
    return u ^ (((unsigned)((int)u >> 31)) | 0x80000000u);
}
__device__ __forceinline__ float unflip(unsigned k) {
    unsigned u = (k & 0x80000000u) ? (k ^ 0x80000000u) : ~k;
    return __uint_as_float(u);
}

/* boundary b in [lo0,hi0]:
   v>0: pred(m)=(v*s[m]>=T) true for m<b ; count = b
   v<0: pred(m)=(v*s[m]>=T) true for m>=b; count = N-b */
__device__ __forceinline__ int bs_bound(float v, float T, const float* s,
                                        int lo0, int hi0) {
    int lo = lo0, hi = hi0;
    if (v > 0.0f) {
        while (lo < hi) { int m = (lo + hi) >> 1; if (v * s[m] >= T) lo = m + 1; else hi = m; }
    } else {
        while (lo < hi) { int m = (lo + hi) >> 1; if (v * s[m] >= T) hi = m; else lo = m + 1; }
    }
    return lo;
}
__device__ __forceinline__ unsigned b2c(float v, int b) {
    return (v > 0.0f) ? (unsigned)b : (unsigned)(N - b);
}

__global__ void k_select(const float* __restrict__ p) {
    extern __shared__ unsigned char sm[];
    unsigned* s_off = (unsigned*)sm;                 /* [16384] 64KB; later tie buf */
    float*    s_val = (float*)(sm + 65536);          /* [8192] 32KB */
    int*      s_idx = (int*)(sm + 98304);            /* [8192] 32KB */
    unsigned* s_tie = s_off;
    __shared__ unsigned cur[1024];
    __shared__ unsigned s_red[32];
    __shared__ unsigned s_lo, s_hi, s_dec, s_total, s_ntie, s_cut;

    const int t = threadIdx.x;   /* 1024 threads */

    /* ---- zero hist ---- */
    for (int i = t; i < NBINS; i += 1024) s_off[i] = 0u;
    __syncthreads();

    /* ---- hist (hi-14 key) ---- */
    float pv[8];
    #pragma unroll
    for (int j = 0; j < 8; j++) {
        pv[j] = p[t + j * 1024];
        atomicAdd(&s_off[fkey(pv[j]) >> KSHIFT], 1u);
    }
    __syncthreads();

    /* ---- suffix scan -> s_off[b] = #keys in bins strictly above b ---- */
    {
        const int base = t * 16;
        unsigned h[16]; unsigned ct = 0;
        #pragma unroll
        for (int j = 0; j < 16; j++) { h[j] = s_off[base + j]; ct += h[j]; }
        cur[t] = ct; __syncthreads();
        for (int d = 1; d < 1024; d <<= 1) {
            unsigned v2 = cur[t] + ((t + d < 1024) ? cur[t + d] : 0u);
            __syncthreads(); cur[t] = v2; __syncthreads();
        }
        unsigned g = cur[t] - ct;            /* keys in chunks above this one */
        for (int j = 15; j >= 0; j--) {      /* higher bin = earlier position */
            s_off[base + j] = g;
            g += h[j];
        }
    }
    __syncthreads();

    /* ---- scatter (descending by bin) ---- */
    #pragma unroll
    for (int j = 0; j < 8; j++) {
        unsigned b = fkey(pv[j]) >> KSHIFT;
        unsigned pos = atomicAdd(&s_off[b], 1u);
        s_val[pos] = pv[j];
        s_idx[pos] = t + j * 1024;
    }
    __syncthreads();

    /* ---- per-run insertion fix (runs = equal hi-14 key) ---- */
    for (int i = t; i < N; i += 1024) {
        unsigned bi = fkey(s_val[i]) >> KSHIFT;
        if (i > 0 && (fkey(s_val[i - 1]) >> KSHIFT) == bi) continue; /* not run start */
        int e = i + 1;
        while (e < N && (fkey(s_val[e]) >> KSHIFT) == bi) e++;
        for (int a = i + 1; a < e; a++) {
            float kv = s_val[a]; int ki = s_idx[a];
            int j = a - 1;
            while (j >= i && s_val[j] < kv) {
                s_val[j + 1] = s_val[j]; s_idx[j + 1] = s_idx[j]; j--;
            }
            s_val[j + 1] = kv; s_idx[j + 1] = ki;
        }
    }
    __syncthreads();

    /* contiguous rows for this thread */
    float rv[8];
    #pragma unroll
    for (int j = 0; j < 8; j++) rv[j] = s_val[8 * t + j];

    /* ---- bisection with sign-aware warm-start boundary intervals ----
       invariant: true boundary for any T inside current bracket lies in
       [bmin[j], bmax[j]]. v>0: b decreasing in T; v<0: b increasing in T. */
    int bmin[8], bmax[8];
    #pragma unroll
    for (int j = 0; j < 8; j++) { bmin[j] = 0; bmax[j] = N; }
    if (t == 0) { s_lo = 0x80000000u; s_hi = 0xFFFFFFFFu; }
    __syncthreads();

    for (;;) {
        unsigned lo = s_lo, hi = s_hi;
        if (hi - lo <= 1u) break;
        unsigned mid = lo + ((hi - lo) >> 1);
        float T = unflip(mid);
        int bm[8]; unsigned c = 0;
        #pragma unroll
        for (int j = 0; j < 8; j++) {
            float v = rv[j];
            int b = (v == 0.0f) ? 0 : bs_bound(v, T, s_val, bmin[j], bmax[j]);
            bm[j] = b;
            unsigned cj = (v == 0.0f) ? 0u : b2c(v, b);
            if (v != 0.0f && v * v >= T) cj -= 1u;   /* drop diagonal */
            c += cj;
        }
        #pragma unroll
        for (int d = 16; d > 0; d >>= 1) c += __shfl_down_sync(0xffffffffu, c, d);
        if ((t & 31) == 0) s_red[t >> 5] = c;
        __syncthreads();
        if (t == 0) {
            unsigned s = 0;
            for (int i = 0; i < 32; i++) s += s_red[i];
            if (s >= KTOP) { s_lo = mid; s_dec = 1u; }
            else           { s_hi = mid; s_dec = 0u; }
        }
        __syncthreads();
        unsigned dec = s_dec;
        #pragma unroll
        for (int j = 0; j < 8; j++) {
            float v = rv[j];
            if (v == 0.0f) continue;
            if (dec) {  /* T range now (mid, hi] */
                if (v > 0.0f) bmax[j] = bm[j]; else bmin[j] = bm[j];
            } else {    /* T range now [lo, mid) */
                if (v > 0.0f) bmin[j] = bm[j]; else bmax[j] = bm[j];
            }
        }
        __syncthreads();
    }
    const unsigned Tk = s_lo;
    const float thr  = unflip(Tk);
    const float thr1 = unflip(Tk + 1u);

    /* ---- strict-above count at thr1 -> tie budget r ---- */
    {
        unsigned c = 0;
        #pragma unroll
        for (int j = 0; j < 8; j++) {
            float v = rv[j];
            if (v == 0.0f) continue;
            int b = bs_bound(v, thr1, s_val, bmin[j], bmax[j]);
            unsigned cj = b2c(v, b);
            if (v * v >= thr1) cj -= 1u;
            c += cj;
        }
        #pragma unroll
        for (int d = 16; d > 0; d >>= 1) c += __shfl_down_sync(0xffffffffu, c, d);
        if ((t & 31) == 0) s_red[t >> 5] = c;
        __syncthreads();
        if (t == 0) {
            unsigned s = 0;
            for (int i = 0; i < 32; i++) s += s_red[i];
            s_total = s;
            s_ntie = 0;
        }
        __syncthreads();
    }
    const unsigned r = KTOP - s_total;

    /* ---- collect tie pairs (value == thr), skip diagonal ---- */
    #pragma unroll
    for (int j = 0; j < 8; j++) {
        int row = 8 * t + j;
        float v = rv[j];
        if (v == 0.0f) continue;
        int bA = bs_bound(v, thr,  s_val, 0, N);
        int bB = bs_bound(v, thr1, s_val, 0, N);
        int m0, m1;
        if (v > 0.0f) { m0 = bB; m1 = bA; } else { m0 = bA; m1 = bB; }
        if (m1 <= m0) continue;
        unsigned fb = ((unsigned)s_idx[row]) << 13;
        for (int m = m0; m < m1; m++) {
            if (m == row) continue;
            unsigned pos = atomicAdd(&s_ntie, 1u);
            if (pos < TIECAP) s_tie[pos] = fb + (unsigned)s_idx[m];
        }
    }
    __syncthreads();

    /* ---- cut = tie flat with rank r (include ties with flat < cut) ---- */
    unsigned nt = min(s_ntie, (unsigned)TIECAP);
    if (t == 0) s_cut = (r >= nt) ? 0xFFFFFFFFu : 0u;
    __syncthreads();
    if (r < nt) {
        for (unsigned i = t; i < nt; i += 1024) {
            unsigned x = s_tie[i];
            unsigned rk = 0;
            for (unsigned j2 = 0; j2 < nt; j2++) rk += (s_tie[j2] < x) ? 1u : 0u;
            if (rk == r) s_cut = x;
        }
    }
    __syncthreads();
    if (t == 0) { g_thr = thr; g_cut = s_cut; }
}

/* ---- fused output pass ---- */
__device__ __forceinline__ float edgev(float v, float thr, unsigned flat, unsigned cut, bool diag) {
    bool ok = ((v > thr) | ((v == thr) & (flat < cut))) & (!diag);
    return ok ? 1.0f : 0.0f;
}

__global__ void k_out(const float* __restrict__ p, float4* __restrict__ out) {
    int row = blockIdx.y;
    float pi = __ldg(p + row);
    float thr = g_thr;
    unsigned cut = g_cut;
    const float4* __restrict__ q4 = (const float4*)p;
    int f0 = blockIdx.x * 1024 + threadIdx.x;
    unsigned fbase = ((unsigned)row) << 13;
    unsigned outrow = ((unsigned)row) << 11;
    #pragma unroll
    for (int k = 0; k < 4; k++) {
        int f = f0 + k * 256;
        float4 q = __ldg(q4 + f);
        unsigned j0 = ((unsigned)f) << 2;
        float4 o;
        o.x = edgev(pi * q.x, thr, fbase + j0 + 0u, cut, (j0 + 0u) == (unsigned)row);
        o.y = edgev(pi * q.y, thr, fbase + j0 + 1u, cut, (j0 + 1u) == (unsigned)row);
        o.z = edgev(pi * q.z, thr, fbase + j0 + 2u, cut, (j0 + 2u) == (unsigned)row);
        o.w = edgev(pi * q.w, thr, fbase + j0 + 3u, cut, (j0 + 3u) == (unsigned)row);
        out[outrow + (unsigned)f] = o;
    }
}

extern "C" void kernel_launch(void* const* d_in, const int* in_sizes, int n_in,
                              void* d_out, int out_size) {
    const float* p = (const float*)d_in[0];
    float* out = (float*)d_out;
    (void)in_sizes; (void)n_in; (void)out_size;

    const int SMEM = 65536 + 32768 + 32768;   /* 131072 B dynamic */
    cudaFuncSetAttribute(k_select, cudaFuncAttributeMaxDynamicSharedMemorySize, SMEM);

    k_select<<<1, 1024, SMEM>>>(p);

    dim3 grid(2, N);
    k_out<<<grid, 256>>>(p, (float4*)out);
}